// round 9
// baseline (speedup 1.0000x reference)
#include <cuda_runtime.h>
#include <math.h>

typedef unsigned long long ull;

#define TPB 128

// ---------------- constant-memory weights (27744 B) ----------------
// cW1u: conv1 [half][c][tap][6 ull]  : 2268 ull = 18144 B (pairs of 10-oc half, 1 ull pad)
// cW2u: conv2 [oc][q][15 ull]        : 1200 ull = 9600 B
__constant__ ull cW1u[2268];
__constant__ ull cW2u[1200];

__device__ float g_pack[6936];

// ---------------- shared memory float offsets (60.9 KB -> 2 blocks/SM) ----------------
#define FC1P_OFF  0        // fc1 [j1][32] (cols 0..29, pad 0) : 3840
#define FC1OH_OFF 3840     // fc1 one-hot cols [j1][8] : 960
#define FC2T_OFF  4800     // fc2 transposed [j1][84] : 10080
#define FC3_OFF   14880    // 84
#define B1_OFF    14964    // 20
#define B2P_OFF   14984    // 32
#define FB1_OFF   15016    // 120
#define FB2_OFF   15136    // 84
#define FB3_OFF   15220    // 1 (+3 pad)
#define SMEM_FLOATS 15224
#define SMEM_BYTES  (SMEM_FLOATS * 4)

__device__ __forceinline__ ull ffma2(ull a, ull b, ull c) {
    ull d; asm("fma.rn.f32x2 %0,%1,%2,%3;" : "=l"(d) : "l"(a), "l"(b), "l"(c)); return d;
}
__device__ __forceinline__ ull pack2(float lo, float hi) {
    ull d; asm("mov.b64 %0,{%1,%2};" : "=l"(d) : "f"(lo), "f"(hi)); return d;
}
__device__ __forceinline__ void unpack2(ull v, float& lo, float& hi) {
    asm("mov.b64 {%0,%1},%2;" : "=f"(lo), "=f"(hi) : "l"(v));
}
__device__ __forceinline__ float lrelu(float v) { return fmaxf(v, 0.2f * v); }

// ==================== repack kernel: gmem weights -> g_pack ====================
__global__ void repack_kernel(const float* __restrict__ c1w,
                              const float* __restrict__ c2w)
{
    int i = blockIdx.x * 256 + threadIdx.x;
    if (i < 4536) {                       // cW1u floats [half][c][tap][12]
        int half = i / 2268; int r = i % 2268;
        int c = r / 108; int r2 = r % 108;
        int tap = r2 / 12; int j2 = r2 % 12;
        g_pack[i] = (j2 < 10) ? c1w[((half * 10 + j2) * 21 + c) * 9 + tap] : 0.f;
    } else if (i < 6936) {                // cW2u floats [oc][q][30]
        int j = i - 4536;
        int oc = j / 120; int rem = j % 120; int q = rem / 30; int oc2 = rem % 30;
        g_pack[i] = c2w[(oc2 * 20 + oc) * 4 + q];
    }
}

// conv1: 4 channels (c0..c0+3) x 9 taps, features in fq[] registers (by position).
// Each weight (c,tap) loaded ONCE and reused across all valid positions.
__device__ __forceinline__ void conv4(int half, int c0,
                                      const float4 (&fq)[9],
                                      ull (&o2)[5][9]) {
#pragma unroll
    for (int cc = 0; cc < 4; ++cc) {
        ull fp[9];
#pragma unroll
        for (int p = 0; p < 9; ++p) {
            float fv = (cc == 0) ? fq[p].x : (cc == 1) ? fq[p].y
                     : (cc == 2) ? fq[p].z : fq[p].w;
            fp[p] = pack2(fv, fv);
        }
        const ull* wbase = cW1u + (size_t)((half * 21 + c0 + cc) * 9) * 6;
#pragma unroll
        for (int t = 0; t < 9; ++t) {
            const int dy = 1 - t / 3, dx = 1 - t % 3;
            const ull* wr = wbase + t * 6;
            ulonglong2 wa = *reinterpret_cast<const ulonglong2*>(wr);
            ulonglong2 wb = *reinterpret_cast<const ulonglong2*>(wr + 2);
            ull wc = wr[4];
#pragma unroll
            for (int py = 0; py < 3; ++py) {
#pragma unroll
                for (int px = 0; px < 3; ++px) {
                    const int qy = py + dy, qx = px + dx;
                    if (qy < 0 || qy > 2 || qx < 0 || qx > 2) continue;
                    const int p = py * 3 + px, q = qy * 3 + qx;
                    o2[0][q] = ffma2(wa.x, fp[p], o2[0][q]);
                    o2[1][q] = ffma2(wa.y, fp[p], o2[1][q]);
                    o2[2][q] = ffma2(wb.x, fp[p], o2[2][q]);
                    o2[3][q] = ffma2(wb.y, fp[p], o2[3][q]);
                    o2[4][q] = ffma2(wc,   fp[p], o2[4][q]);
                }
            }
        }
    }
}

// conv1 mask channel (c = 20), features from mfp[] registers.
__device__ __forceinline__ void convmask(int half, const float (&mfp)[9],
                                         ull (&o2)[5][9]) {
    ull fp[9];
#pragma unroll
    for (int p = 0; p < 9; ++p) fp[p] = pack2(mfp[p], mfp[p]);
    const ull* wbase = cW1u + (size_t)((half * 21 + 20) * 9) * 6;
#pragma unroll
    for (int t = 0; t < 9; ++t) {
        const int dy = 1 - t / 3, dx = 1 - t % 3;
        const ull* wr = wbase + t * 6;
        ulonglong2 wa = *reinterpret_cast<const ulonglong2*>(wr);
        ulonglong2 wb = *reinterpret_cast<const ulonglong2*>(wr + 2);
        ull wc = wr[4];
#pragma unroll
        for (int py = 0; py < 3; ++py) {
#pragma unroll
            for (int px = 0; px < 3; ++px) {
                const int qy = py + dy, qx = px + dx;
                if (qy < 0 || qy > 2 || qx < 0 || qx > 2) continue;
                const int p = py * 3 + px, q = qy * 3 + qx;
                o2[0][q] = ffma2(wa.x, fp[p], o2[0][q]);
                o2[1][q] = ffma2(wa.y, fp[p], o2[1][q]);
                o2[2][q] = ffma2(wb.x, fp[p], o2[2][q]);
                o2[3][q] = ffma2(wb.y, fp[p], o2[3][q]);
                o2[4][q] = ffma2(wc,   fp[p], o2[4][q]);
            }
        }
    }
}

// lrelu + 2x2/s1 maxpool + conv2 accumulate for one conv1 channel
__device__ __forceinline__ void poolc2(float r0, float r1, float r2,
                                       float r3, float r4, float r5,
                                       float r6, float r7, float r8,
                                       int oc, ull (&aa)[16])
{
    r0 = lrelu(r0); r1 = lrelu(r1); r2 = lrelu(r2);
    r3 = lrelu(r3); r4 = lrelu(r4); r5 = lrelu(r5);
    r6 = lrelu(r6); r7 = lrelu(r7); r8 = lrelu(r8);
    float p0 = fmaxf(fmaxf(r0, r1), fmaxf(r3, r4));
    float p1 = fmaxf(fmaxf(r1, r2), fmaxf(r4, r5));
    float p2 = fmaxf(fmaxf(r3, r4), fmaxf(r6, r7));
    float p3 = fmaxf(fmaxf(r4, r5), fmaxf(r7, r8));
#pragma unroll
    for (int q = 0; q < 4; ++q) {
        float pv = (q == 0) ? p0 : (q == 1) ? p1 : (q == 2) ? p2 : p3;
        ull pq = pack2(pv, pv);
        const int base = (oc * 4 + q) * 15;
#pragma unroll
        for (int g = 0; g < 15; ++g) {
            ull w = cW2u[base + g];
            aa[g] = ffma2(w, pq, aa[g]);
        }
    }
}

__global__ void __launch_bounds__(TPB, 2)
disc_kernel(const int* __restrict__ state, const int* __restrict__ des,
            const int* __restrict__ act,
            const int* __restrict__ asp, const int* __restrict__ pm,
            const float* __restrict__ path_feature,
            const float* __restrict__ link_feature,
            const float* __restrict__ c1b, const float* __restrict__ c2b,
            const float* __restrict__ f1w, const float* __restrict__ f1b,
            const float* __restrict__ f2w, const float* __restrict__ f2b,
            const float* __restrict__ f3w, const float* __restrict__ f3b,
            float* __restrict__ out, int B)
{
    extern __shared__ float sm[];
    const int tid = threadIdx.x;

    // ---------- stage fc weights + small vectors into smem ----------
    for (int i = tid; i < 3840; i += TPB) {            // FC1 [j1][32]
        int j = i / 32; int k = i % 32;
        sm[FC1P_OFF + i] = (k < 30) ? f1w[j * 38 + k] : 0.f;
    }
    for (int i = tid; i < 960; i += TPB) {             // FC1 one-hot cols
        int j = i / 8; int a8 = i % 8;
        sm[FC1OH_OFF + i] = f1w[j * 38 + 30 + a8];
    }
    for (int i = tid; i < 10080; i += TPB) {           // FC2 transposed [j1][84]
        int j1 = i / 84; int j2 = i % 84;
        sm[FC2T_OFF + i] = f2w[j2 * 120 + j1];
    }
    for (int i = tid; i < 84; i += TPB) sm[FC3_OFF + i] = f3w[i];
    if (tid < 20) sm[B1_OFF + tid] = c1b[tid];
    if (tid < 32) sm[B2P_OFF + tid] = (tid < 30) ? c2b[tid] : 0.f;
    if (tid < 120) sm[FB1_OFF + tid] = f1b[tid];
    if (tid < 84) sm[FB2_OFF + tid] = f2b[tid];
    if (tid == 0) sm[FB3_OFF] = f3b[0];
    __syncthreads();

    const int b = blockIdx.x * TPB + tid;
    if (b >= B) return;

    const int s = state[b];
    const size_t dd = (size_t)des[b];
    const int a = act[b];

    // position-indexed neighbor ids and masks: nnp[p] = asp[s*9 + NEW_INDEX[p]]
    int nnp[9];
    float mfp[9];
    {
        const int NI0 = 7, NI1 = 0, NI2 = 1, NI3 = 6, NI4 = 8,
                  NI5 = 2, NI6 = 5, NI7 = 4, NI8 = 3;
        nnp[0] = asp[s * 9 + NI0]; mfp[0] = (float)pm[s * 9 + NI0];
        nnp[1] = asp[s * 9 + NI1]; mfp[1] = (float)pm[s * 9 + NI1];
        nnp[2] = asp[s * 9 + NI2]; mfp[2] = (float)pm[s * 9 + NI2];
        nnp[3] = asp[s * 9 + NI3]; mfp[3] = (float)pm[s * 9 + NI3];
        nnp[4] = asp[s * 9 + NI4]; mfp[4] = (float)pm[s * 9 + NI4];
        nnp[5] = asp[s * 9 + NI5]; mfp[5] = (float)pm[s * 9 + NI5];
        nnp[6] = asp[s * 9 + NI6]; mfp[6] = (float)pm[s * 9 + NI6];
        nnp[7] = asp[s * 9 + NI7]; mfp[7] = (float)pm[s * 9 + NI7];
        nnp[8] = asp[s * 9 + NI8]; mfp[8] = (float)pm[s * 9 + NI8];
    }

    ull o2[5][9];    // conv1 accumulators, one 10-oc half at a time
    ull aa[16];      // conv2 accumulators

#define GPF(K) { \
    _Pragma("unroll") \
    for (int p = 0; p < 9; ++p) \
        fq[p] = reinterpret_cast<const float4*>( \
            path_feature + ((size_t)nnp[p] * 300 + dd) * 12)[K]; }
#define GLF(K) { \
    _Pragma("unroll") \
    for (int p = 0; p < 9; ++p) \
        fq[p] = reinterpret_cast<const float4*>( \
            link_feature + (size_t)nnp[p] * 8)[K]; }

#define HALF_CONV(H) { \
    float4 fq[9]; \
    GPF(0); conv4(H, 0,  fq, o2); \
    GPF(1); conv4(H, 4,  fq, o2); \
    GPF(2); conv4(H, 8,  fq, o2); \
    GLF(0); conv4(H, 12, fq, o2); \
    GLF(1); conv4(H, 16, fq, o2); \
    convmask(H, mfp, o2); }

#define POOLHALF(OCBASE) { \
    _Pragma("unroll") \
    for (int u = 0; u < 5; ++u) { \
        float l0,h0,l1,h1,l2,h2,l3,h3,l4,h4,l5,h5,l6,h6,l7,h7,l8,h8; \
        unpack2(o2[u][0], l0, h0); unpack2(o2[u][1], l1, h1); unpack2(o2[u][2], l2, h2); \
        unpack2(o2[u][3], l3, h3); unpack2(o2[u][4], l4, h4); unpack2(o2[u][5], l5, h5); \
        unpack2(o2[u][6], l6, h6); unpack2(o2[u][7], l7, h7); unpack2(o2[u][8], l8, h8); \
        poolc2(l0,l1,l2,l3,l4,l5,l6,l7,l8, (OCBASE) + 2*u,     aa); \
        poolc2(h0,h1,h2,h3,h4,h5,h6,h7,h8, (OCBASE) + 2*u + 1, aa); } }

    // ---------- half 0 : oc 0..9 ----------
#pragma unroll
    for (int u = 0; u < 5; ++u) {
        ull bb = pack2(sm[B1_OFF + 2 * u], sm[B1_OFF + 2 * u + 1]);
#pragma unroll
        for (int q = 0; q < 9; ++q) o2[u][q] = bb;
    }
    HALF_CONV(0);
#pragma unroll
    for (int j = 0; j < 16; ++j)
        aa[j] = pack2(sm[B2P_OFF + 2 * j], sm[B2P_OFF + 2 * j + 1]);
    POOLHALF(0);

    // ---------- half 1 : oc 10..19 (re-gather, L2 hits) ----------
#pragma unroll
    for (int u = 0; u < 5; ++u) {
        ull bb = pack2(sm[B1_OFF + 10 + 2 * u], sm[B1_OFF + 11 + 2 * u]);
#pragma unroll
        for (int q = 0; q < 9; ++q) o2[u][q] = bb;
    }
    HALF_CONV(1);
    POOLHALF(10);

#undef GPF
#undef GLF
#undef HALF_CONV
#undef POOLHALF

    // ---------- fc1 + fc2 fused (fc2 from smem) ----------
    ull x2[16];
#pragma unroll
    for (int j = 0; j < 15; ++j) {
        float lo, hi; unpack2(aa[j], lo, hi);
        x2[j] = pack2(lrelu(lo), lrelu(hi));
    }
    x2[15] = pack2(0.f, 0.f);

    ull hh[42];
#pragma unroll
    for (int j = 0; j < 42; ++j)
        hh[j] = pack2(sm[FB2_OFF + 2 * j], sm[FB2_OFF + 2 * j + 1]);

#pragma unroll 2
    for (int j1 = 0; j1 < 120; ++j1) {
        const ulonglong2* wp = reinterpret_cast<const ulonglong2*>(sm + FC1P_OFF + j1 * 32);
        ull t0 = 0ull, t1 = 0ull, t2 = 0ull, t3 = 0ull;
#pragma unroll
        for (int g = 0; g < 4; ++g) {
            ulonglong2 wA = wp[2 * g], wB = wp[2 * g + 1];
            t0 = ffma2(wA.x, x2[4 * g],     t0);
            t1 = ffma2(wA.y, x2[4 * g + 1], t1);
            t2 = ffma2(wB.x, x2[4 * g + 2], t2);
            t3 = ffma2(wB.y, x2[4 * g + 3], t3);
        }
        float s0, s1, s2, s3, s4, s5, s6, s7;
        unpack2(t0, s0, s1); unpack2(t1, s2, s3); unpack2(t2, s4, s5); unpack2(t3, s6, s7);
        float t = sm[FB1_OFF + j1] + sm[FC1OH_OFF + j1 * 8 + a]
                + (((s0 + s1) + (s2 + s3)) + ((s4 + s5) + (s6 + s7)));
        t = lrelu(t);
        ull tt = pack2(t, t);
        const ulonglong2* w2p = reinterpret_cast<const ulonglong2*>(sm + FC2T_OFF + j1 * 84);
#pragma unroll
        for (int g = 0; g < 21; ++g) {
            ulonglong2 w = w2p[g];
            hh[2 * g]     = ffma2(w.x, tt, hh[2 * g]);
            hh[2 * g + 1] = ffma2(w.y, tt, hh[2 * g + 1]);
        }
    }

    // ---------- fc3 + sigmoid ----------
    float z0 = 0.f, z1 = 0.f, z2 = 0.f, z3 = 0.f;
#pragma unroll
    for (int g = 0; g < 42; ++g) {
        float lo, hi; unpack2(hh[g], lo, hi);
        lo = lrelu(lo); hi = lrelu(hi);
        if (g & 1) { z2 += lo * sm[FC3_OFF + 2 * g]; z3 += hi * sm[FC3_OFF + 2 * g + 1]; }
        else       { z0 += lo * sm[FC3_OFF + 2 * g]; z1 += hi * sm[FC3_OFF + 2 * g + 1]; }
    }
    float z = sm[FB3_OFF] + ((z0 + z1) + (z2 + z3));
    out[b] = 1.f / (1.f + expf(-z));
}

extern "C" void kernel_launch(void* const* d_in, const int* in_sizes, int n_in,
                              void* d_out, int out_size)
{
    const int*   state = (const int*)d_in[0];
    const int*   des   = (const int*)d_in[1];
    const int*   act   = (const int*)d_in[2];
    const int*   asp   = (const int*)d_in[3];
    const int*   pm    = (const int*)d_in[4];
    const float* pf    = (const float*)d_in[5];
    const float* lf    = (const float*)d_in[6];
    const float* c1w   = (const float*)d_in[7];
    const float* c1b   = (const float*)d_in[8];
    const float* c2w   = (const float*)d_in[9];
    const float* c2b   = (const float*)d_in[10];
    const float* f1w   = (const float*)d_in[11];
    const float* f1b   = (const float*)d_in[12];
    const float* f2w   = (const float*)d_in[13];
    const float* f2b   = (const float*)d_in[14];
    const float* f3w   = (const float*)d_in[15];
    const float* f3b   = (const float*)d_in[16];

    const int B = in_sizes[0];
    float* out = (float*)d_out;

    repack_kernel<<<(6936 + 255) / 256, 256>>>(c1w, c2w);

    void* ps = nullptr;
    cudaGetSymbolAddress(&ps, g_pack);
    const char* pc = (const char*)ps;
    cudaMemcpyToSymbolAsync(cW1u, pc,            4536 * 4, 0, cudaMemcpyDeviceToDevice);
    cudaMemcpyToSymbolAsync(cW2u, pc + 4536 * 4, 2400 * 4, 0, cudaMemcpyDeviceToDevice);

    cudaFuncSetAttribute(disc_kernel, cudaFuncAttributeMaxDynamicSharedMemorySize, SMEM_BYTES);

    const int grid = (B + TPB - 1) / TPB;
    disc_kernel<<<grid, TPB, SMEM_BYTES>>>(state, des, act, asp, pm, pf, lf,
                                           c1b, c2b, f1w, f1b, f2w, f2b, f3w, f3b,
                                           out, B);
}

// round 10
// speedup vs baseline: 1.3468x; 1.3468x over previous
#include <cuda_runtime.h>
#include <math.h>

typedef unsigned long long ull;

#define TPB 192

// ---- shared memory float offsets (89280 B -> 2 blocks/SM, 12 warps) ----
#define W1_OFF    0        // conv1 [half][c][k][12] : 2*21*9*12 = 4536
#define W2_OFF    4536     // conv2 [oc][q][32pad]   : 20*4*32  = 2560
#define FC1P_OFF  7096     // fc1 [j1][32] (cols 0..29, pad 0) : 3840
#define FC1OH_OFF 10936    // fc1 one-hot cols [j1][8] : 960
#define FC2T_OFF  11896    // fc2 transposed [j1][84] : 10080
#define FC3_OFF   21976    // 84
#define B1_OFF    22060    // 20
#define B2P_OFF   22080    // 32
#define FB1_OFF   22112    // 120
#define FB2_OFF   22232    // 84
#define FB3_OFF   22316    // 1 (+3 pad)
#define SMEM_FLOATS 22320
#define SMEM_BYTES  (SMEM_FLOATS * 4)

__device__ __forceinline__ ull ffma2(ull a, ull b, ull c) {
    ull d; asm("fma.rn.f32x2 %0,%1,%2,%3;" : "=l"(d) : "l"(a), "l"(b), "l"(c)); return d;
}
__device__ __forceinline__ ull pack2(float lo, float hi) {
    ull d; asm("mov.b64 %0,{%1,%2};" : "=l"(d) : "f"(lo), "f"(hi)); return d;
}
__device__ __forceinline__ void unpack2(ull v, float& lo, float& hi) {
    asm("mov.b64 {%0,%1},%2;" : "=f"(lo), "=f"(hi) : "l"(v));
}
__device__ __forceinline__ float lrelu(float v) { return fmaxf(v, 0.2f * v); }

// conv1, ONE input channel, all 9 taps, weights loaded once per tap and
// reused across every valid output position. fp[p] = packed feature at
// input position p. o2 = 5 oc-pair accumulators x 9 output positions.
__device__ __forceinline__ void conv_c(const float* __restrict__ wb,
                                       const ull (&fp)[9], ull (&o2)[5][9]) {
#pragma unroll
    for (int k = 0; k < 9; ++k) {
        const int ky = k / 3, kx = k % 3;
        const float* wr = wb + k * 12;
        ulonglong2 wa = *reinterpret_cast<const ulonglong2*>(wr);
        ulonglong2 wv = *reinterpret_cast<const ulonglong2*>(wr + 4);
        ull wc = *reinterpret_cast<const ull*>(wr + 8);
#pragma unroll
        for (int y = 0; y < 3; ++y) {
            const int iy = y + ky - 1;
            if (iy < 0 || iy > 2) continue;
#pragma unroll
            for (int x = 0; x < 3; ++x) {
                const int ix = x + kx - 1;
                if (ix < 0 || ix > 2) continue;
                const int q = y * 3 + x, p = iy * 3 + ix;
                o2[0][q] = ffma2(wa.x, fp[p], o2[0][q]);
                o2[1][q] = ffma2(wa.y, fp[p], o2[1][q]);
                o2[2][q] = ffma2(wv.x, fp[p], o2[2][q]);
                o2[3][q] = ffma2(wv.y, fp[p], o2[3][q]);
                o2[4][q] = ffma2(wc,   fp[p], o2[4][q]);
            }
        }
    }
}

// lrelu + 2x2/s1 maxpool + conv2 accumulate for one conv1 channel (W2 in smem)
__device__ __forceinline__ void poolc2(const float* __restrict__ sm,
                                       float r0, float r1, float r2,
                                       float r3, float r4, float r5,
                                       float r6, float r7, float r8,
                                       int oc, ull (&aa)[16])
{
    r0 = lrelu(r0); r1 = lrelu(r1); r2 = lrelu(r2);
    r3 = lrelu(r3); r4 = lrelu(r4); r5 = lrelu(r5);
    r6 = lrelu(r6); r7 = lrelu(r7); r8 = lrelu(r8);
    float p0 = fmaxf(fmaxf(r0, r1), fmaxf(r3, r4));
    float p1 = fmaxf(fmaxf(r1, r2), fmaxf(r4, r5));
    float p2 = fmaxf(fmaxf(r3, r4), fmaxf(r6, r7));
    float p3 = fmaxf(fmaxf(r4, r5), fmaxf(r7, r8));
#pragma unroll
    for (int q = 0; q < 4; ++q) {
        float pv = (q == 0) ? p0 : (q == 1) ? p1 : (q == 2) ? p2 : p3;
        ull pq = pack2(pv, pv);
        const ulonglong2* wp = reinterpret_cast<const ulonglong2*>(
            sm + W2_OFF + (oc * 4 + q) * 32);
#pragma unroll
        for (int g = 0; g < 8; ++g) {
            ulonglong2 w = wp[g];
            aa[2 * g]     = ffma2(w.x, pq, aa[2 * g]);
            aa[2 * g + 1] = ffma2(w.y, pq, aa[2 * g + 1]);
        }
    }
}

__global__ void __launch_bounds__(TPB, 2)
disc_kernel(const int* __restrict__ state, const int* __restrict__ des,
            const int* __restrict__ act,
            const int* __restrict__ asp, const int* __restrict__ pm,
            const float* __restrict__ path_feature,
            const float* __restrict__ link_feature,
            const float* __restrict__ c1w, const float* __restrict__ c1b,
            const float* __restrict__ c2w, const float* __restrict__ c2b,
            const float* __restrict__ f1w, const float* __restrict__ f1b,
            const float* __restrict__ f2w, const float* __restrict__ f2b,
            const float* __restrict__ f3w, const float* __restrict__ f3b,
            float* __restrict__ out, int B)
{
    extern __shared__ float sm[];
    const int tid = threadIdx.x;

    // ---------- stage + repack weights ----------
    for (int i = tid; i < 4536; i += TPB) {            // W1 [half][c][k][12]
        int half = i / 2268; int r = i % 2268;
        int c = r / 108; int r2 = r % 108;
        int k = r2 / 12; int j = r2 % 12;
        sm[W1_OFF + i] = (j < 10) ? c1w[((half * 10 + j) * 21 + c) * 9 + k] : 0.f;
    }
    for (int i = tid; i < 2560; i += TPB) {            // W2 [oc][q][32pad]
        int oc = i / 128; int rem = i % 128; int q = rem / 32; int oc2 = rem % 32;
        sm[W2_OFF + i] = (oc2 < 30) ? c2w[(oc2 * 20 + oc) * 4 + q] : 0.f;
    }
    for (int i = tid; i < 3840; i += TPB) {            // FC1 [j1][32]
        int j = i / 32; int k = i % 32;
        sm[FC1P_OFF + i] = (k < 30) ? f1w[j * 38 + k] : 0.f;
    }
    for (int i = tid; i < 960; i += TPB) {             // FC1 one-hot cols
        int j = i / 8; int a8 = i % 8;
        sm[FC1OH_OFF + i] = f1w[j * 38 + 30 + a8];
    }
    for (int i = tid; i < 10080; i += TPB) {           // FC2 transposed [j1][84]
        int j1 = i / 84; int j2 = i % 84;
        sm[FC2T_OFF + i] = f2w[j2 * 120 + j1];
    }
    for (int i = tid; i < 84; i += TPB) sm[FC3_OFF + i] = f3w[i];
    if (tid < 20) sm[B1_OFF + tid] = c1b[tid];
    if (tid < 32) sm[B2P_OFF + tid] = (tid < 30) ? c2b[tid] : 0.f;
    if (tid < 120) sm[FB1_OFF + tid] = f1b[tid];
    if (tid < 84) sm[FB2_OFF + tid] = f2b[tid];
    if (tid == 0) sm[FB3_OFF] = f3b[0];
    __syncthreads();

    const int b = blockIdx.x * TPB + tid;
    if (b >= B) return;

    const int s = state[b];
    const size_t dd = (size_t)des[b];
    const int a = act[b];

    // position p uses neighbor NEW_INDEX[p]
    const int NI[9] = {7, 0, 1, 6, 8, 2, 5, 4, 3};
    int nnp[9];
#pragma unroll
    for (int p = 0; p < 9; ++p) nnp[p] = asp[s * 9 + NI[p]];

    ull o2[5][9];
    ull aa[16];

    // one conv half: duos of channels via float2 loads, weights reused per (c,k)
#define HALF_CONV(H) { \
    const float* wbH = sm + W1_OFF + (H) * 2268; \
    _Pragma("unroll 1") \
    for (int d = 0; d < 6; ++d) {      /* path channels 0..11 */ \
        float2 f2[9]; \
        _Pragma("unroll") \
        for (int p = 0; p < 9; ++p) \
            f2[p] = reinterpret_cast<const float2*>( \
                path_feature + ((size_t)nnp[p] * 300 + dd) * 12)[d]; \
        ull fp[9]; \
        _Pragma("unroll") \
        for (int p = 0; p < 9; ++p) fp[p] = pack2(f2[p].x, f2[p].x); \
        conv_c(wbH + (2 * d) * 108, fp, o2); \
        _Pragma("unroll") \
        for (int p = 0; p < 9; ++p) fp[p] = pack2(f2[p].y, f2[p].y); \
        conv_c(wbH + (2 * d + 1) * 108, fp, o2); \
    } \
    _Pragma("unroll 1") \
    for (int d = 0; d < 4; ++d) {      /* link channels 12..19 */ \
        float2 f2[9]; \
        _Pragma("unroll") \
        for (int p = 0; p < 9; ++p) \
            f2[p] = reinterpret_cast<const float2*>( \
                link_feature + (size_t)nnp[p] * 8)[d]; \
        ull fp[9]; \
        _Pragma("unroll") \
        for (int p = 0; p < 9; ++p) fp[p] = pack2(f2[p].x, f2[p].x); \
        conv_c(wbH + (12 + 2 * d) * 108, fp, o2); \
        _Pragma("unroll") \
        for (int p = 0; p < 9; ++p) fp[p] = pack2(f2[p].y, f2[p].y); \
        conv_c(wbH + (12 + 2 * d + 1) * 108, fp, o2); \
    } \
    {                                   /* mask channel 20 */ \
        ull fp[9]; \
        _Pragma("unroll") \
        for (int p = 0; p < 9; ++p) { \
            float mv = (float)pm[s * 9 + NI[p]]; \
            fp[p] = pack2(mv, mv); \
        } \
        conv_c(wbH + 20 * 108, fp, o2); \
    } }

#define POOLHALF(OCBASE) { \
    _Pragma("unroll") \
    for (int u = 0; u < 5; ++u) { \
        float l0,h0,l1,h1,l2,h2,l3,h3,l4,h4,l5,h5,l6,h6,l7,h7,l8,h8; \
        unpack2(o2[u][0], l0, h0); unpack2(o2[u][1], l1, h1); unpack2(o2[u][2], l2, h2); \
        unpack2(o2[u][3], l3, h3); unpack2(o2[u][4], l4, h4); unpack2(o2[u][5], l5, h5); \
        unpack2(o2[u][6], l6, h6); unpack2(o2[u][7], l7, h7); unpack2(o2[u][8], l8, h8); \
        poolc2(sm, l0,l1,l2,l3,l4,l5,l6,l7,l8, (OCBASE) + 2*u,     aa); \
        poolc2(sm, h0,h1,h2,h3,h4,h5,h6,h7,h8, (OCBASE) + 2*u + 1, aa); } }

    // ---------- half 0 : oc 0..9 ----------
#pragma unroll
    for (int u = 0; u < 5; ++u) {
        ull bb = pack2(sm[B1_OFF + 2 * u], sm[B1_OFF + 2 * u + 1]);
#pragma unroll
        for (int q = 0; q < 9; ++q) o2[u][q] = bb;
    }
    HALF_CONV(0);
#pragma unroll
    for (int j = 0; j < 16; ++j)
        aa[j] = pack2(sm[B2P_OFF + 2 * j], sm[B2P_OFF + 2 * j + 1]);
    POOLHALF(0);

    // ---------- half 1 : oc 10..19 (features re-read, L1/L2 hits) ----------
#pragma unroll
    for (int u = 0; u < 5; ++u) {
        ull bb = pack2(sm[B1_OFF + 10 + 2 * u], sm[B1_OFF + 11 + 2 * u]);
#pragma unroll
        for (int q = 0; q < 9; ++q) o2[u][q] = bb;
    }
    HALF_CONV(1);
    POOLHALF(10);

#undef HALF_CONV
#undef POOLHALF

    // ---------- fc1 + fc2 fused ----------
    ull x2[16];
#pragma unroll
    for (int j = 0; j < 15; ++j) {
        float lo, hi; unpack2(aa[j], lo, hi);
        x2[j] = pack2(lrelu(lo), lrelu(hi));
    }
    x2[15] = pack2(0.f, 0.f);

    ull hh[42];
#pragma unroll
    for (int j = 0; j < 42; ++j)
        hh[j] = pack2(sm[FB2_OFF + 2 * j], sm[FB2_OFF + 2 * j + 1]);

#pragma unroll 2
    for (int j1 = 0; j1 < 120; ++j1) {
        const ulonglong2* wp = reinterpret_cast<const ulonglong2*>(sm + FC1P_OFF + j1 * 32);
        ull t0 = 0ull, t1 = 0ull, t2 = 0ull, t3 = 0ull;
#pragma unroll
        for (int g = 0; g < 4; ++g) {
            ulonglong2 wA = wp[2 * g], wB = wp[2 * g + 1];
            t0 = ffma2(wA.x, x2[4 * g],     t0);
            t1 = ffma2(wA.y, x2[4 * g + 1], t1);
            t2 = ffma2(wB.x, x2[4 * g + 2], t2);
            t3 = ffma2(wB.y, x2[4 * g + 3], t3);
        }
        float s0, s1, s2, s3, s4, s5, s6, s7;
        unpack2(t0, s0, s1); unpack2(t1, s2, s3); unpack2(t2, s4, s5); unpack2(t3, s6, s7);
        float t = sm[FB1_OFF + j1] + sm[FC1OH_OFF + j1 * 8 + a]
                + (((s0 + s1) + (s2 + s3)) + ((s4 + s5) + (s6 + s7)));
        t = lrelu(t);
        ull tt = pack2(t, t);
        const ulonglong2* w2p = reinterpret_cast<const ulonglong2*>(sm + FC2T_OFF + j1 * 84);
#pragma unroll
        for (int g = 0; g < 21; ++g) {
            ulonglong2 w = w2p[g];
            hh[2 * g]     = ffma2(w.x, tt, hh[2 * g]);
            hh[2 * g + 1] = ffma2(w.y, tt, hh[2 * g + 1]);
        }
    }

    // ---------- fc3 + sigmoid ----------
    float z0 = 0.f, z1 = 0.f, z2 = 0.f, z3 = 0.f;
#pragma unroll
    for (int g = 0; g < 42; ++g) {
        float lo, hi; unpack2(hh[g], lo, hi);
        lo = lrelu(lo); hi = lrelu(hi);
        if (g & 1) { z2 += lo * sm[FC3_OFF + 2 * g]; z3 += hi * sm[FC3_OFF + 2 * g + 1]; }
        else       { z0 += lo * sm[FC3_OFF + 2 * g]; z1 += hi * sm[FC3_OFF + 2 * g + 1]; }
    }
    float z = sm[FB3_OFF] + ((z0 + z1) + (z2 + z3));
    out[b] = 1.f / (1.f + expf(-z));
}

extern "C" void kernel_launch(void* const* d_in, const int* in_sizes, int n_in,
                              void* d_out, int out_size)
{
    const int*   state = (const int*)d_in[0];
    const int*   des   = (const int*)d_in[1];
    const int*   act   = (const int*)d_in[2];
    const int*   asp   = (const int*)d_in[3];
    const int*   pm    = (const int*)d_in[4];
    const float* pf    = (const float*)d_in[5];
    const float* lf    = (const float*)d_in[6];
    const float* c1w   = (const float*)d_in[7];
    const float* c1b   = (const float*)d_in[8];
    const float* c2w   = (const float*)d_in[9];
    const float* c2b   = (const float*)d_in[10];
    const float* f1w   = (const float*)d_in[11];
    const float* f1b   = (const float*)d_in[12];
    const float* f2w   = (const float*)d_in[13];
    const float* f2b   = (const float*)d_in[14];
    const float* f3w   = (const float*)d_in[15];
    const float* f3b   = (const float*)d_in[16];

    const int B = in_sizes[0];
    float* out = (float*)d_out;

    cudaFuncSetAttribute(disc_kernel, cudaFuncAttributeMaxDynamicSharedMemorySize, SMEM_BYTES);

    const int grid = (B + TPB - 1) / TPB;
    disc_kernel<<<grid, TPB, SMEM_BYTES>>>(state, des, act, asp, pm, pf, lf,
                                           c1w, c1b, c2w, c2b,
                                           f1w, f1b, f2w, f2b, f3w, f3b,
                                           out, B);
}